// round 1
// baseline (speedup 1.0000x reference)
#include <cuda_runtime.h>
#include <math.h>

#define Bb   4
#define Hh   12
#define Nn   2048
#define Mm   512
#define Dd   64
#define DIMc 768
#define SCALEc 0.125f
#define NEGc  (-1e9f)

#define O1_OFF 0
#define O2_OFF 6291456
#define O3_OFF 7864320
#define O4_OFF 7867392

#define MASK_ELEMS 50331648  // B*H*N*M

// ---------------- scratch (device globals; no allocation allowed) ----------
__device__ float g_tq[Bb*Hh*Nn*Dd];
__device__ float g_tk[Bb*Hh*Nn*Dd];
__device__ float g_tv[Bb*Hh*Nn*Dd];
__device__ float g_kq[Bb*Hh*Mm*Dd];
__device__ float g_kk[Bb*Hh*Mm*Dd];
__device__ float g_kv[Bb*Hh*Mm*Dd];
__device__ float g_cq[Bb*Hh*Dd];
__device__ float g_cdk[Bb*Hh*Dd];
__device__ float g_cdv[Bb*Hh*Dd];
__device__ float g_att[Bb*Hh*Nn*Dd];
__device__ float g_kout[Bb*Hh*Mm*Dd];
__device__ float g_cout[Bb*DIMc];
__device__ unsigned char g_mask[MASK_ELEMS];
__device__ int g_mode;

// ---------------- mask dtype sniffing + normalization ----------------------
// mode 0: int32 (words 0/1), mode 1: float32 (0.0f/1.0f), mode 2: uint8
__global__ void detect_mask_kernel(const void* m) {
    const unsigned int* w = (const unsigned int*)m;
    __shared__ int notint, notf32;
    if (threadIdx.x == 0) { notint = 0; notf32 = 0; }
    __syncthreads();
    for (int i = threadIdx.x; i < 1024; i += blockDim.x) {
        unsigned int v = w[i];
        if (v > 1u) notint = 1;
        if (v != 0u && v != 0x3F800000u) notf32 = 1;
    }
    __syncthreads();
    if (threadIdx.x == 0) g_mode = notint ? (notf32 ? 2 : 1) : 0;
}

__global__ void norm_mask_kernel(const void* m) {
    int gid = blockIdx.x * blockDim.x + threadIdx.x;   // one gid = 4 elements
    if (gid * 4 >= MASK_ELEMS) return;
    int mode = g_mode;
    uchar4 r;
    int base = gid * 4;
    if (mode == 0) {
        const int* p = (const int*)m;
        r.x = p[base+0] != 0; r.y = p[base+1] != 0;
        r.z = p[base+2] != 0; r.w = p[base+3] != 0;
    } else if (mode == 1) {
        const float* p = (const float*)m;
        r.x = p[base+0] != 0.f; r.y = p[base+1] != 0.f;
        r.z = p[base+2] != 0.f; r.w = p[base+3] != 0.f;
    } else {
        const unsigned char* p = (const unsigned char*)m;
        r.x = p[base+0] != 0; r.y = p[base+1] != 0;
        r.z = p[base+2] != 0; r.w = p[base+3] != 0;
    }
    ((uchar4*)g_mask)[gid] = r;
}

// ---------------- big fp32 GEMM: QKV projection -----------------------------
// Y = X(rows x 768) @ W_qkv(768 x 2304), scattered into per-head q/k/v scratch
// which: 0 -> x (L=2048), 1 -> kx (L=512), 2 -> clst (L=1)
__global__ __launch_bounds__(256) void gemm_qkv_kernel(
    const float* __restrict__ X, const float* __restrict__ W,
    int rows, int L, int which)
{
    __shared__ float Ast[16][129];   // [k][m], stride 129 -> conflict-free
    __shared__ float Bs[16][128];    // [k][c]
    int m0 = blockIdx.y * 128, c0 = blockIdx.x * 128;
    int tid = threadIdx.x, tx = tid & 15, ty = tid >> 4;
    float acc[8][8];
#pragma unroll
    for (int r = 0; r < 8; r++)
#pragma unroll
        for (int c = 0; c < 8; c++) acc[r][c] = 0.f;

    for (int k0 = 0; k0 < 768; k0 += 16) {
#pragma unroll
        for (int i = 0; i < 8; i++) {
            int li = tid + i * 256;
            int m = li >> 4, k = li & 15;
            float v = 0.f;
            if (m0 + m < rows) v = X[(m0 + m) * 768 + k0 + k];
            Ast[k][m] = v;
        }
#pragma unroll
        for (int i = 0; i < 8; i++) {
            int li = tid + i * 256;
            int k = li >> 7, c = li & 127;
            Bs[k][c] = W[(k0 + k) * 2304 + c0 + c];
        }
        __syncthreads();
#pragma unroll
        for (int k = 0; k < 16; k++) {
            float a[8], bb[8];
#pragma unroll
            for (int r = 0; r < 8; r++) a[r] = Ast[k][ty * 8 + r];
            const float4* bp = reinterpret_cast<const float4*>(&Bs[k][tx * 8]);
            float4 b0 = bp[0], b1 = bp[1];
            bb[0]=b0.x; bb[1]=b0.y; bb[2]=b0.z; bb[3]=b0.w;
            bb[4]=b1.x; bb[5]=b1.y; bb[6]=b1.z; bb[7]=b1.w;
#pragma unroll
            for (int r = 0; r < 8; r++)
#pragma unroll
                for (int c = 0; c < 8; c++) acc[r][c] = fmaf(a[r], bb[c], acc[r][c]);
        }
        __syncthreads();
    }

    float* dq = (which == 0) ? g_tq : (which == 1) ? g_kq : g_cq;
    float* dk = (which == 0) ? g_tk : (which == 1) ? g_kk : g_cdk;
    float* dv = (which == 0) ? g_tv : (which == 1) ? g_kv : g_cdv;
#pragma unroll
    for (int r = 0; r < 8; r++) {
        int row = m0 + ty * 8 + r;
        if (row >= rows) continue;
        int b = row / L, n = row % L;
#pragma unroll
        for (int c = 0; c < 8; c++) {
            int col = c0 + tx * 8 + c;
            int s = col / 768;
            int rem = col - s * 768;
            int h = rem >> 6, d = rem & 63;
            float* dst = (s == 0) ? dq : (s == 1) ? dk : dv;
            dst[((b * Hh + h) * L + n) * Dd + d] = acc[r][c];
        }
    }
}

// ---------------- output projection GEMM ------------------------------------
// O = merge(att)(rows x 768) @ W_out(768 x 768) + b_out
// which: 0 -> g_att (L=2048), 1 -> g_kout (L=512)
__global__ __launch_bounds__(256) void gemm_proj_kernel(
    const float* __restrict__ W, const float* __restrict__ bias,
    float* __restrict__ O, int rows, int L, int which)
{
    __shared__ float Ast[16][129];
    __shared__ float Bs[16][128];
    const float* A = (which == 0) ? g_att : g_kout;
    int m0 = blockIdx.y * 128, c0 = blockIdx.x * 128;
    int tid = threadIdx.x, tx = tid & 15, ty = tid >> 4;
    float acc[8][8];
#pragma unroll
    for (int r = 0; r < 8; r++)
#pragma unroll
        for (int c = 0; c < 8; c++) acc[r][c] = 0.f;

    for (int k0 = 0; k0 < 768; k0 += 16) {
#pragma unroll
        for (int i = 0; i < 8; i++) {
            int li = tid + i * 256;
            int m = li >> 4, k = li & 15;
            int row = m0 + m, gk = k0 + k;
            int b = row / L, n = row % L;
            int h = gk >> 6, d = gk & 63;
            Ast[k][m] = A[((b * Hh + h) * L + n) * Dd + d];
        }
#pragma unroll
        for (int i = 0; i < 8; i++) {
            int li = tid + i * 256;
            int k = li >> 7, c = li & 127;
            Bs[k][c] = W[(k0 + k) * 768 + c0 + c];
        }
        __syncthreads();
#pragma unroll
        for (int k = 0; k < 16; k++) {
            float a[8], bb[8];
#pragma unroll
            for (int r = 0; r < 8; r++) a[r] = Ast[k][ty * 8 + r];
            const float4* bp = reinterpret_cast<const float4*>(&Bs[k][tx * 8]);
            float4 b0 = bp[0], b1 = bp[1];
            bb[0]=b0.x; bb[1]=b0.y; bb[2]=b0.z; bb[3]=b0.w;
            bb[4]=b1.x; bb[5]=b1.y; bb[6]=b1.z; bb[7]=b1.w;
#pragma unroll
            for (int r = 0; r < 8; r++)
#pragma unroll
                for (int c = 0; c < 8; c++) acc[r][c] = fmaf(a[r], bb[c], acc[r][c]);
        }
        __syncthreads();
    }
#pragma unroll
    for (int r = 0; r < 8; r++) {
        int row = m0 + ty * 8 + r;
#pragma unroll
        for (int c = 0; c < 8; c++) {
            int col = c0 + tx * 8 + c;
            O[row * 768 + col] = acc[r][c] + bias[col];
        }
    }
}

// ---------------- branch 1: t_q vs k_k, dual softmax, attn_hot, PV ----------
// grid (N/64, B*H), 256 threads, dyn smem ~182 KB
__global__ __launch_bounds__(256) void branch1_kernel(
    const float* __restrict__ krd, float* __restrict__ o4)
{
    extern __shared__ float sm[];
    float* Qs   = sm;              // 64*65
    float* KV   = Qs + 64 * 65;    // 64*65 (Ks then Vs)
    float* Ps   = KV + 64 * 65;    // 64*65
    float* dots = Ps + 64 * 65;    // 64*513
    float* rmax = dots + 64 * 513; // 64
    float* rs1  = rmax + 64;       // 64
    float* rs2  = rs1 + 64;        // 64

    int bh = blockIdx.y;
    int i0 = blockIdx.x * 64;
    int tid = threadIdx.x, tx = tid & 15, ty = tid >> 4;

    for (int li = tid; li < 4096; li += 256) {
        int i = li >> 6, d = li & 63;
        Qs[i * 65 + d] = g_tq[(bh * Nn + i0 + i) * Dd + d];
    }

    // phase A: dots = Q @ K^T * scale
    for (int jt = 0; jt < 8; jt++) {
        int j0 = jt * 64;
        __syncthreads();
        for (int li = tid; li < 4096; li += 256) {
            int j = li >> 6, d = li & 63;
            KV[j * 65 + d] = g_kk[(bh * Mm + j0 + j) * Dd + d];
        }
        __syncthreads();
        float acc[4][4];
#pragma unroll
        for (int r = 0; r < 4; r++)
#pragma unroll
            for (int c = 0; c < 4; c++) acc[r][c] = 0.f;
#pragma unroll 16
        for (int k = 0; k < 64; k++) {
            float a[4], b[4];
#pragma unroll
            for (int r = 0; r < 4; r++) a[r] = Qs[(ty * 4 + r) * 65 + k];
#pragma unroll
            for (int c = 0; c < 4; c++) b[c] = KV[(tx * 4 + c) * 65 + k];
#pragma unroll
            for (int r = 0; r < 4; r++)
#pragma unroll
                for (int c = 0; c < 4; c++) acc[r][c] = fmaf(a[r], b[c], acc[r][c]);
        }
#pragma unroll
        for (int r = 0; r < 4; r++)
#pragma unroll
            for (int c = 0; c < 4; c++)
                dots[(ty * 4 + r) * 513 + j0 + tx * 4 + c] = acc[r][c] * SCALEc;
    }
    __syncthreads();

    // mask fixup (coalesced over j)
    for (int idx = tid; idx < 64 * 512; idx += 256) {
        int i = idx >> 9, j = idx & 511;
        if (g_mask[(bh * Nn + i0 + i) * Mm + j]) dots[i * 513 + j] = NEGc;
    }
    __syncthreads();

    // row stats: max, 1/sum(exp), 1/sum(exp(24x))
    {
        int w = tid >> 5, lane = tid & 31;
        for (int r = 0; r < 8; r++) {
            int i = w * 8 + r;
            float mx = -INFINITY;
            for (int j = lane; j < 512; j += 32) mx = fmaxf(mx, dots[i * 513 + j]);
#pragma unroll
            for (int o = 16; o; o >>= 1) mx = fmaxf(mx, __shfl_xor_sync(0xffffffffu, mx, o));
            float s1 = 0.f, s2 = 0.f;
            for (int j = lane; j < 512; j += 32) {
                float xv = dots[i * 513 + j] - mx;
                s1 += __expf(xv);
                s2 += __expf(24.f * xv);
            }
#pragma unroll
            for (int o = 16; o; o >>= 1) {
                s1 += __shfl_xor_sync(0xffffffffu, s1, o);
                s2 += __shfl_xor_sync(0xffffffffu, s2, o);
            }
            if (lane == 0) { rmax[i] = mx; rs1[i] = 1.f / s1; rs2[i] = 1.f / s2; }
        }
    }

    // phase C: attn_hot out + P, PV accumulate
    float acc2[4][4];
#pragma unroll
    for (int r = 0; r < 4; r++)
#pragma unroll
        for (int c = 0; c < 4; c++) acc2[r][c] = 0.f;

    for (int jt = 0; jt < 8; jt++) {
        int j0 = jt * 64;
        __syncthreads();
        for (int li = tid; li < 4096; li += 256) {
            int j = li >> 6, d = li & 63;
            KV[j * 65 + d] = g_kv[(bh * Mm + j0 + j) * Dd + d];
        }
        for (int idx = tid; idx < 4096; idx += 256) {
            int jj = idx >> 6, ii = idx & 63;
            float xv = dots[ii * 513 + j0 + jj] - rmax[ii];
            int gi = (bh * Mm + j0 + jj) * Nn + i0 + ii;
            float kr = krd[gi];
            o4[gi] = __expf(24.f * xv) * rs2[ii] * kr;
            Ps[jj * 65 + ii] = __expf(xv) * rs1[ii] * kr;
        }
        __syncthreads();
#pragma unroll 16
        for (int k = 0; k < 64; k++) {
            float a[4], b[4];
#pragma unroll
            for (int r = 0; r < 4; r++) a[r] = Ps[k * 65 + ty * 4 + r];
#pragma unroll
            for (int c = 0; c < 4; c++) b[c] = KV[k * 65 + tx * 4 + c];
#pragma unroll
            for (int r = 0; r < 4; r++)
#pragma unroll
                for (int c = 0; c < 4; c++) acc2[r][c] = fmaf(a[r], b[c], acc2[r][c]);
        }
    }
#pragma unroll
    for (int r = 0; r < 4; r++)
#pragma unroll
        for (int c = 0; c < 4; c++)
            g_att[(bh * Nn + i0 + ty * 4 + r) * Dd + tx * 4 + c] = acc2[r][c];
}

// ---------------- branch 2: k_q vs t_k, flash-style online softmax ----------
// grid (M/64, B*H), 256 threads, dyn smem ~84 KB
__global__ __launch_bounds__(256) void branch2_kernel(const float* __restrict__ krd)
{
    extern __shared__ float sm[];
    float* Qs  = sm;             // 64*65
    float* Ks  = Qs + 64 * 65;
    float* Vs  = Ks + 64 * 65;
    float* Ss  = Vs + 64 * 65;
    float* Ps  = Ss + 64 * 65;
    float* mxA = Ps + 64 * 65;   // 64
    float* dnA = mxA + 64;       // 64
    float* fsc = dnA + 64;       // 64

    int bh = blockIdx.y;
    int i0 = blockIdx.x * 64;    // m-query tile
    int tid = threadIdx.x, tx = tid & 15, ty = tid >> 4;
    int w = tid >> 5, lane = tid & 31;

    for (int li = tid; li < 4096; li += 256) {
        int i = li >> 6, d = li & 63;
        Qs[i * 65 + d] = g_kq[(bh * Mm + i0 + i) * Dd + d];
    }
    if (tid < 64) { mxA[tid] = -INFINITY; dnA[tid] = 0.f; }

    float acc[4][4];
#pragma unroll
    for (int r = 0; r < 4; r++)
#pragma unroll
        for (int c = 0; c < 4; c++) acc[r][c] = 0.f;

    for (int nt = 0; nt < 32; nt++) {
        int n0 = nt * 64;
        __syncthreads();
        for (int li = tid; li < 4096; li += 256) {
            int j = li >> 6, d = li & 63;
            Ks[j * 65 + d] = g_tk[(bh * Nn + n0 + j) * Dd + d];
            Vs[j * 65 + d] = g_tv[(bh * Nn + n0 + j) * Dd + d];
        }
        __syncthreads();
        // S = Q @ K^T * scale
        {
            float sac[4][4];
#pragma unroll
            for (int r = 0; r < 4; r++)
#pragma unroll
                for (int c = 0; c < 4; c++) sac[r][c] = 0.f;
#pragma unroll 16
            for (int k = 0; k < 64; k++) {
                float a[4], b[4];
#pragma unroll
                for (int r = 0; r < 4; r++) a[r] = Qs[(ty * 4 + r) * 65 + k];
#pragma unroll
                for (int c = 0; c < 4; c++) b[c] = Ks[(tx * 4 + c) * 65 + k];
#pragma unroll
                for (int r = 0; r < 4; r++)
#pragma unroll
                    for (int c = 0; c < 4; c++) sac[r][c] = fmaf(a[r], b[c], sac[r][c]);
            }
#pragma unroll
            for (int r = 0; r < 4; r++)
#pragma unroll
                for (int c = 0; c < 4; c++)
                    Ss[(ty * 4 + r) * 65 + tx * 4 + c] = sac[r][c] * SCALEc;
        }
        __syncthreads();
        // mask (transposed view of att_mask; coalesced over ii)
        for (int idx = tid; idx < 4096; idx += 256) {
            int jj = idx >> 6, ii = idx & 63;
            if (g_mask[(bh * Nn + n0 + jj) * Mm + i0 + ii]) Ss[ii * 65 + jj] = NEGc;
        }
        __syncthreads();
        // online softmax row stats
        for (int r = 0; r < 8; r++) {
            int i = w * 8 + r;
            float tmx = -INFINITY;
            for (int j = lane; j < 64; j += 32) tmx = fmaxf(tmx, Ss[i * 65 + j]);
#pragma unroll
            for (int o = 16; o; o >>= 1) tmx = fmaxf(tmx, __shfl_xor_sync(0xffffffffu, tmx, o));
            float om = mxA[i];
            float nm = fmaxf(om, tmx);
            float s = 0.f;
            for (int j = lane; j < 64; j += 32) s += __expf(Ss[i * 65 + j] - nm);
#pragma unroll
            for (int o = 16; o; o >>= 1) s += __shfl_xor_sync(0xffffffffu, s, o);
            if (lane == 0) {
                float f = __expf(om - nm);
                dnA[i] = dnA[i] * f + s;
                mxA[i] = nm;
                fsc[i] = f;
            }
        }
        __syncthreads();
        // P = exp(S - m) * krd   (krd coalesced over jj, Ps stride-65 writes)
        for (int idx = tid; idx < 4096; idx += 256) {
            int ii = idx >> 6, jj = idx & 63;
            float kr = krd[(bh * Mm + i0 + ii) * Nn + n0 + jj];
            Ps[jj * 65 + ii] = __expf(Ss[ii * 65 + jj] - mxA[ii]) * kr;
        }
        __syncthreads();
        // rescale + accumulate P @ V
        float f[4];
#pragma unroll
        for (int r = 0; r < 4; r++) f[r] = fsc[ty * 4 + r];
#pragma unroll
        for (int r = 0; r < 4; r++)
#pragma unroll
            for (int c = 0; c < 4; c++) acc[r][c] *= f[r];
#pragma unroll 16
        for (int k = 0; k < 64; k++) {
            float a[4], b[4];
#pragma unroll
            for (int r = 0; r < 4; r++) a[r] = Ps[k * 65 + ty * 4 + r];
#pragma unroll
            for (int c = 0; c < 4; c++) b[c] = Vs[k * 65 + tx * 4 + c];
#pragma unroll
            for (int r = 0; r < 4; r++)
#pragma unroll
                for (int c = 0; c < 4; c++) acc[r][c] = fmaf(a[r], b[c], acc[r][c]);
        }
    }
    __syncthreads();
#pragma unroll
    for (int r = 0; r < 4; r++) {
        float inv = 1.f / dnA[ty * 4 + r];
#pragma unroll
        for (int c = 0; c < 4; c++)
            g_kout[(bh * Mm + i0 + ty * 4 + r) * Dd + tx * 4 + c] = acc[r][c] * inv;
    }
}

// ---------------- branch 3: cluster query (1 per b,h) -----------------------
__global__ __launch_bounds__(256) void branch3_kernel()
{
    __shared__ float cq[64];
    __shared__ float pb[512];
    __shared__ float red[8];
    __shared__ float outp[256];
    __shared__ float smax, ssum;
    int bh = blockIdx.x;
    int b = bh / Hh, h = bh % Hh;
    int tid = threadIdx.x, w = tid >> 5, lane = tid & 31;

    if (tid < 64) cq[tid] = g_cq[bh * Dd + tid];
    __syncthreads();

    for (int j = tid; j < 512; j += 256) {
        float s = 0.f;
#pragma unroll 16
        for (int d = 0; d < 64; d++) s = fmaf(cq[d], g_kk[(bh * Mm + j) * Dd + d], s);
        s *= SCALEc;
        if (g_mask[(bh * Nn + 0) * Mm + j]) s = NEGc;
        pb[j] = s;
    }
    __syncthreads();
    // max
    float m = -INFINITY;
    for (int j = tid; j < 512; j += 256) m = fmaxf(m, pb[j]);
#pragma unroll
    for (int o = 16; o; o >>= 1) m = fmaxf(m, __shfl_xor_sync(0xffffffffu, m, o));
    if (lane == 0) red[w] = m;
    __syncthreads();
    if (tid == 0) {
        float mm = red[0];
        for (int i = 1; i < 8; i++) mm = fmaxf(mm, red[i]);
        smax = mm;
    }
    __syncthreads();
    // exp + sum
    float sum = 0.f;
    for (int j = tid; j < 512; j += 256) {
        float e = __expf(pb[j] - smax);
        pb[j] = e;
        sum += e;
    }
#pragma unroll
    for (int o = 16; o; o >>= 1) sum += __shfl_xor_sync(0xffffffffu, sum, o);
    if (lane == 0) red[w] = sum;
    __syncthreads();
    if (tid == 0) {
        float s = 0.f;
        for (int i = 0; i < 8; i++) s += red[i];
        ssum = s;
    }
    __syncthreads();
    // weighted V sum
    int d = tid & 63, q = tid >> 6;
    float a = 0.f;
    for (int j = q * 128; j < (q + 1) * 128; j++)
        a = fmaf(pb[j], g_kv[(bh * Mm + j) * Dd + d], a);
    outp[q * 64 + d] = a;
    __syncthreads();
    if (tid < 64) {
        float tot = outp[tid] + outp[64 + tid] + outp[128 + tid] + outp[192 + tid];
        g_cout[b * DIMc + h * Dd + tid] = tot / ssum;
    }
}

// ---------------- cluster projection ----------------------------------------
__global__ __launch_bounds__(256) void cproj_kernel(
    const float* __restrict__ W, const float* __restrict__ bias,
    float* __restrict__ o3)
{
    int gid = blockIdx.x * 256 + threadIdx.x;  // 3072 total
    int b = gid / 768, c = gid % 768;
    float a = bias[c];
    for (int k = 0; k < 768; k++) a = fmaf(g_cout[b * 768 + k], W[k * 768 + c], a);
    o3[gid] = a;
}

// ---------------- launch ----------------------------------------------------
extern "C" void kernel_launch(void* const* d_in, const int* in_sizes, int n_in,
                              void* d_out, int out_size) {
    const float* x    = (const float*)d_in[0];
    const float* kx   = (const float*)d_in[1];
    const float* krd  = (const float*)d_in[2];
    const float* clst = (const float*)d_in[3];
    const void*  amsk = d_in[4];
    const float* Wqkv = (const float*)d_in[5];
    const float* Wout = (const float*)d_in[6];
    const float* bout = (const float*)d_in[7];
    float* out = (float*)d_out;

    float* o1 = out + O1_OFF;
    float* o2 = out + O2_OFF;
    float* o3 = out + O3_OFF;
    float* o4 = out + O4_OFF;

    size_t sm1 = (size_t)(64 * 65 * 3 + 64 * 513 + 192) * 4;  // 182016 B
    size_t sm2 = (size_t)(64 * 65 * 5 + 192) * 4;             //  83968 B
    cudaFuncSetAttribute(branch1_kernel, cudaFuncAttributeMaxDynamicSharedMemorySize, (int)sm1);
    cudaFuncSetAttribute(branch2_kernel, cudaFuncAttributeMaxDynamicSharedMemorySize, (int)sm2);

    detect_mask_kernel<<<1, 256>>>(amsk);
    norm_mask_kernel<<<MASK_ELEMS / 4 / 256, 256>>>(amsk);

    // QKV projections
    gemm_qkv_kernel<<<dim3(18, 64), 256>>>(x,    Wqkv, 8192, 2048, 0);
    gemm_qkv_kernel<<<dim3(18, 16), 256>>>(kx,   Wqkv, 2048,  512, 1);
    gemm_qkv_kernel<<<dim3(18,  1), 256>>>(clst, Wqkv,    4,    1, 2);

    // attention branches
    branch1_kernel<<<dim3(32, 48), 256, sm1>>>(krd, o4);
    branch2_kernel<<<dim3(8,  48), 256, sm2>>>(krd);
    branch3_kernel<<<48, 256>>>();

    // output projections
    gemm_proj_kernel<<<dim3(6, 64), 256>>>(Wout, bout, o1, 8192, 2048, 0);
    gemm_proj_kernel<<<dim3(6, 16), 256>>>(Wout, bout, o2, 2048,  512, 1);
    cproj_kernel<<<12, 256>>>(Wout, bout, o3);
}

// round 5
// speedup vs baseline: 1.5984x; 1.5984x over previous
#include <cuda_runtime.h>
#include <math.h>

#define Bb   4
#define Hh   12
#define Nn   2048
#define Mm   512
#define Dd   64
#define DIMc 768
#define SCALEc 0.125f
#define NEGc  (-1e9f)

#define O1_OFF 0
#define O2_OFF 6291456
#define O3_OFF 7864320
#define O4_OFF 7867392

#define MASK_ELEMS 50331648  // B*H*N*M

// ---------------- f32x2 helpers --------------------------------------------
typedef unsigned long long ull;

__device__ __forceinline__ ull pack2s(float a) {          // (a, a)
    ull r;
    asm("mov.b64 %0, {%1, %1};" : "=l"(r) : "f"(a));
    return r;
}
__device__ __forceinline__ void unpack2(ull v, float& lo, float& hi) {
    asm("mov.b64 {%0, %1}, %2;" : "=f"(lo), "=f"(hi) : "l"(v));
}
#define FMA2(acc, a, b) asm("fma.rn.f32x2 %0, %1, %2, %0;" : "+l"(acc) : "l"(a), "l"(b))
#define MUL2(acc, a)    asm("mul.rn.f32x2 %0, %0, %1;" : "+l"(acc) : "l"(a))

#define CP16(dst, src, pred) \
    asm volatile("cp.async.ca.shared.global [%0], [%1], 16, %2;" \
                 :: "r"(dst), "l"(src), "r"(pred))
#define CP_COMMIT() asm volatile("cp.async.commit_group;")
#define CP_WAIT1()  asm volatile("cp.async.wait_group 1;")
#define CP_WAIT0()  asm volatile("cp.async.wait_group 0;")

// ---------------- scratch (device globals; no allocation allowed) ----------
__device__ float g_tq[Bb*Hh*Nn*Dd];
__device__ float g_tk[Bb*Hh*Nn*Dd];
__device__ float g_tv[Bb*Hh*Nn*Dd];
__device__ float g_kq[Bb*Hh*Mm*Dd];
__device__ float g_kk[Bb*Hh*Mm*Dd];
__device__ float g_kv[Bb*Hh*Mm*Dd];
__device__ float g_cq[Bb*Hh*Dd];
__device__ float g_cdk[Bb*Hh*Dd];
__device__ float g_cdv[Bb*Hh*Dd];
__device__ float g_att[Bb*Hh*Nn*Dd];
__device__ float g_kout[Bb*Hh*Mm*Dd];
__device__ float g_cout[Bb*DIMc];
__device__ unsigned char g_mask[MASK_ELEMS];
__device__ int g_mode;

// ---------------- mask dtype sniffing + normalization ----------------------
__global__ void detect_mask_kernel(const void* m) {
    const unsigned int* w = (const unsigned int*)m;
    __shared__ int notint, notf32;
    if (threadIdx.x == 0) { notint = 0; notf32 = 0; }
    __syncthreads();
    for (int i = threadIdx.x; i < 1024; i += blockDim.x) {
        unsigned int v = w[i];
        if (v > 1u) notint = 1;
        if (v != 0u && v != 0x3F800000u) notf32 = 1;
    }
    __syncthreads();
    if (threadIdx.x == 0) g_mode = notint ? (notf32 ? 2 : 1) : 0;
}

__global__ void norm_mask_kernel(const void* m) {
    int gid = blockIdx.x * blockDim.x + threadIdx.x;
    if (gid * 4 >= MASK_ELEMS) return;
    int mode = g_mode;
    uchar4 r;
    int base = gid * 4;
    if (mode == 0) {
        const int* p = (const int*)m;
        r.x = p[base+0] != 0; r.y = p[base+1] != 0;
        r.z = p[base+2] != 0; r.w = p[base+3] != 0;
    } else if (mode == 1) {
        const float* p = (const float*)m;
        r.x = p[base+0] != 0.f; r.y = p[base+1] != 0.f;
        r.z = p[base+2] != 0.f; r.w = p[base+3] != 0.f;
    } else {
        const unsigned char* p = (const unsigned char*)m;
        r.x = p[base+0] != 0; r.y = p[base+1] != 0;
        r.z = p[base+2] != 0; r.w = p[base+3] != 0;
    }
    ((uchar4*)g_mask)[gid] = r;
}

// ---------------- QKV projection GEMM (cp.async pipelined, FFMA2) -----------
#define AST 20   // A smem row stride (floats), 16B aligned
#define BST 132  // B smem row stride

__global__ __launch_bounds__(256) void gemm_qkv_kernel(
    const float* __restrict__ X, const float* __restrict__ W,
    int rows, int L, int which)
{
    __shared__ float As[2][128 * AST];
    __shared__ float Bs[2][16 * BST];
    int m0 = blockIdx.y * 128, c0 = blockIdx.x * 128;
    int tid = threadIdx.x, tx = tid & 15, ty = tid >> 4;

    ull acc[8][4];
#pragma unroll
    for (int r = 0; r < 8; r++)
#pragma unroll
        for (int c = 0; c < 4; c++) acc[r][c] = 0ull;

    unsigned asm_base[2], bsm_base[2];
#pragma unroll
    for (int s = 0; s < 2; s++) {
        asm_base[s] = (unsigned)__cvta_generic_to_shared(&As[s][0]);
        bsm_base[s] = (unsigned)__cvta_generic_to_shared(&Bs[s][0]);
    }

#define ISSUE_QKV(t, s) do {                                                 \
        int k0_ = (t) * 16;                                                  \
        _Pragma("unroll")                                                    \
        for (int i_ = 0; i_ < 2; i_++) {                                     \
            int cid = tid + i_ * 256;                                        \
            int m_ = cid >> 2, kc = cid & 3;                                 \
            const float* src = X + (size_t)(m0 + m_) * 768 + k0_ + kc * 4;   \
            int pred = (m0 + m_ < rows) ? 16 : 0;                            \
            CP16(asm_base[s] + (m_ * AST + kc * 4) * 4, src, pred);          \
        }                                                                    \
        _Pragma("unroll")                                                    \
        for (int i_ = 0; i_ < 2; i_++) {                                     \
            int cid = tid + i_ * 256;                                        \
            int k_ = cid >> 5, cc = cid & 31;                                \
            const float* src = W + (size_t)(k0_ + k_) * 2304 + c0 + cc * 4;  \
            CP16(bsm_base[s] + (k_ * BST + cc * 4) * 4, src, 16);            \
        }                                                                    \
        CP_COMMIT();                                                         \
    } while (0)

    ISSUE_QKV(0, 0);
    for (int t = 0; t < 48; t++) {
        int cur = t & 1;
        if (t < 47) { ISSUE_QKV(t + 1, cur ^ 1); CP_WAIT1(); }
        else CP_WAIT0();
        __syncthreads();
        const float* A_ = &As[cur][0];
        const float* B_ = &Bs[cur][0];
#pragma unroll
        for (int k = 0; k < 16; k++) {
            ulonglong2 b0 = *(const ulonglong2*)(B_ + k * BST + tx * 8);
            ulonglong2 b1 = *(const ulonglong2*)(B_ + k * BST + tx * 8 + 4);
#pragma unroll
            for (int r = 0; r < 8; r++) {
                ull ap = pack2s(A_[(ty * 8 + r) * AST + k]);
                FMA2(acc[r][0], ap, b0.x);
                FMA2(acc[r][1], ap, b0.y);
                FMA2(acc[r][2], ap, b1.x);
                FMA2(acc[r][3], ap, b1.y);
            }
        }
        __syncthreads();
    }
#undef ISSUE_QKV

    float* dq = (which == 0) ? g_tq : (which == 1) ? g_kq : g_cq;
    float* dk = (which == 0) ? g_tk : (which == 1) ? g_kk : g_cdk;
    float* dv = (which == 0) ? g_tv : (which == 1) ? g_kv : g_cdv;
#pragma unroll
    for (int r = 0; r < 8; r++) {
        int row = m0 + ty * 8 + r;
        if (row >= rows) continue;
        int b = row / L, n = row % L;
#pragma unroll
        for (int c2 = 0; c2 < 4; c2++) {
            float v0, v1;
            unpack2(acc[r][c2], v0, v1);
#pragma unroll
            for (int u = 0; u < 2; u++) {
                int col = c0 + tx * 8 + c2 * 2 + u;
                float v = u ? v1 : v0;
                int s = col / 768;
                int rem = col - s * 768;
                int h = rem >> 6, d = rem & 63;
                float* dst = (s == 0) ? dq : (s == 1) ? dk : dv;
                dst[((b * Hh + h) * L + n) * Dd + d] = v;
            }
        }
    }
}

// ---------------- output projection GEMM (cp.async pipelined, FFMA2) --------
__global__ __launch_bounds__(256) void gemm_proj_kernel(
    const float* __restrict__ W, const float* __restrict__ bias,
    float* __restrict__ O, int rows, int L, int which)
{
    __shared__ float As[2][128 * AST];
    __shared__ float Bs[2][16 * BST];
    const float* A = (which == 0) ? g_att : g_kout;
    int m0 = blockIdx.y * 128, c0 = blockIdx.x * 128;
    int tid = threadIdx.x, tx = tid & 15, ty = tid >> 4;

    ull acc[8][4];
#pragma unroll
    for (int r = 0; r < 8; r++)
#pragma unroll
        for (int c = 0; c < 4; c++) acc[r][c] = 0ull;

    unsigned asm_base[2], bsm_base[2];
#pragma unroll
    for (int s = 0; s < 2; s++) {
        asm_base[s] = (unsigned)__cvta_generic_to_shared(&As[s][0]);
        bsm_base[s] = (unsigned)__cvta_generic_to_shared(&Bs[s][0]);
    }

#define ISSUE_PRJ(t, s) do {                                                  \
        int k0_ = (t) * 16;                                                   \
        _Pragma("unroll")                                                     \
        for (int i_ = 0; i_ < 2; i_++) {                                      \
            int cid = tid + i_ * 256;                                         \
            int m_ = cid >> 2, kc = cid & 3;                                  \
            int row = m0 + m_, kg = k0_ + kc * 4;                             \
            int b_ = row / L, n_ = row % L;                                   \
            int h_ = kg >> 6, d_ = kg & 63;                                   \
            const float* src = A + ((size_t)(b_ * Hh + h_) * L + n_) * 64 + d_;\
            CP16(asm_base[s] + (m_ * AST + kc * 4) * 4, src, 16);             \
        }                                                                     \
        _Pragma("unroll")                                                     \
        for (int i_ = 0; i_ < 2; i_++) {                                      \
            int cid = tid + i_ * 256;                                         \
            int k_ = cid >> 5, cc = cid & 31;                                 \
            const float* src = W + (size_t)(k0_ + k_) * 768 + c0 + cc * 4;    \
            CP16(bsm_base[s] + (k_ * BST + cc * 4) * 4, src, 16);             \
        }                                                                     \
        CP_COMMIT();                                                          \
    } while (0)

    ISSUE_PRJ(0, 0);
    for (int t = 0; t < 48; t++) {
        int cur = t & 1;
        if (t < 47) { ISSUE_PRJ(t + 1, cur ^ 1); CP_WAIT1(); }
        else CP_WAIT0();
        __syncthreads();
        const float* A_ = &As[cur][0];
        const float* B_ = &Bs[cur][0];
#pragma unroll
        for (int k = 0; k < 16; k++) {
            ulonglong2 b0 = *(const ulonglong2*)(B_ + k * BST + tx * 8);
            ulonglong2 b1 = *(const ulonglong2*)(B_ + k * BST + tx * 8 + 4);
#pragma unroll
            for (int r = 0; r < 8; r++) {
                ull ap = pack2s(A_[(ty * 8 + r) * AST + k]);
                FMA2(acc[r][0], ap, b0.x);
                FMA2(acc[r][1], ap, b0.y);
                FMA2(acc[r][2], ap, b1.x);
                FMA2(acc[r][3], ap, b1.y);
            }
        }
        __syncthreads();
    }
#undef ISSUE_PRJ

#pragma unroll
    for (int r = 0; r < 8; r++) {
        int row = m0 + ty * 8 + r;
#pragma unroll
        for (int c2 = 0; c2 < 4; c2++) {
            float v0, v1;
            unpack2(acc[r][c2], v0, v1);
            int col = c0 + tx * 8 + c2 * 2;
            O[row * 768 + col]     = v0 + bias[col];
            O[row * 768 + col + 1] = v1 + bias[col + 1];
        }
    }
}

// ---------------- branch 1: t_q vs k_k, dual softmax, attn_hot, PV ----------
#define TS 66   // attention smem stride (even -> 8B aligned pairs)
__global__ __launch_bounds__(256) void branch1_kernel(
    const float* __restrict__ krd, float* __restrict__ o4)
{
    extern __shared__ float sm[];
    float* Qs   = sm;              // 64*66 [i][k]
    float* KT   = Qs + 64 * TS;    // 64*66: phase A [d][j]; phase C [j][d]
    float* Ps   = KT + 64 * TS;    // 64*66 [j][i]
    float* dots = Ps + 64 * TS;    // 64*513 (logits -> exp values)
    float* rs1  = dots + 64 * 513; // 64
    float* rs2  = rs1 + 64;        // 64

    int bh = blockIdx.y;
    int i0 = blockIdx.x * 64;
    int tid = threadIdx.x, tx = tid & 15, ty = tid >> 4;

    for (int li = tid; li < 4096; li += 256) {
        int i = li >> 6, d = li & 63;
        Qs[i * TS + d] = g_tq[(bh * Nn + i0 + i) * Dd + d];
    }

    // phase A: dots = Q @ K^T * scale  (K stored k-major: KT[d][j])
    for (int jt = 0; jt < 8; jt++) {
        int j0 = jt * 64;
        __syncthreads();
        for (int li = tid; li < 4096; li += 256) {
            int j = li >> 6, d = li & 63;
            KT[d * TS + j] = g_kk[(bh * Mm + j0 + j) * Dd + d];
        }
        __syncthreads();
        ull acc[4][2];
#pragma unroll
        for (int r = 0; r < 4; r++) { acc[r][0] = 0ull; acc[r][1] = 0ull; }
#pragma unroll 16
        for (int k = 0; k < 64; k++) {
            ull b0 = *(const ull*)(KT + k * TS + tx * 4);
            ull b1 = *(const ull*)(KT + k * TS + tx * 4 + 2);
#pragma unroll
            for (int r = 0; r < 4; r++) {
                ull ap = pack2s(Qs[(ty * 4 + r) * TS + k]);
                FMA2(acc[r][0], ap, b0);
                FMA2(acc[r][1], ap, b1);
            }
        }
#pragma unroll
        for (int r = 0; r < 4; r++) {
            float v0, v1, v2, v3;
            unpack2(acc[r][0], v0, v1);
            unpack2(acc[r][1], v2, v3);
            float* dp = dots + (ty * 4 + r) * 513 + j0 + tx * 4;
            dp[0] = v0 * SCALEc; dp[1] = v1 * SCALEc;
            dp[2] = v2 * SCALEc; dp[3] = v3 * SCALEc;
        }
    }
    __syncthreads();

    // mask fixup
    for (int idx = tid; idx < 64 * 512; idx += 256) {
        int i = idx >> 9, j = idx & 511;
        if (g_mask[(bh * Nn + i0 + i) * Mm + j]) dots[i * 513 + j] = NEGc;
    }
    __syncthreads();

    // row stats: max, then e = exp(x-max) stored in-place, sums of e and e^24
    {
        int w = tid >> 5, lane = tid & 31;
        for (int r = 0; r < 8; r++) {
            int i = w * 8 + r;
            float mx = -INFINITY;
            for (int j = lane; j < 512; j += 32) mx = fmaxf(mx, dots[i * 513 + j]);
#pragma unroll
            for (int o = 16; o; o >>= 1) mx = fmaxf(mx, __shfl_xor_sync(0xffffffffu, mx, o));
            float s1 = 0.f, s2 = 0.f;
            for (int j = lane; j < 512; j += 32) {
                float e = __expf(dots[i * 513 + j] - mx);
                float e2 = e * e, e4 = e2 * e2, e8 = e4 * e4, e16 = e8 * e8;
                s1 += e;
                s2 += e16 * e8;
                dots[i * 513 + j] = e;
            }
#pragma unroll
            for (int o = 16; o; o >>= 1) {
                s1 += __shfl_xor_sync(0xffffffffu, s1, o);
                s2 += __shfl_xor_sync(0xffffffffu, s2, o);
            }
            if (lane == 0) { rs1[i] = 1.f / s1; rs2[i] = 1.f / s2; }
        }
    }

    // phase C: attn_hot out + P build, PV accumulate
    ull acc2[4][2];
#pragma unroll
    for (int r = 0; r < 4; r++) { acc2[r][0] = 0ull; acc2[r][1] = 0ull; }

    for (int jt = 0; jt < 8; jt++) {
        int j0 = jt * 64;
        __syncthreads();
        for (int li = tid; li < 4096; li += 256) {
            int j = li >> 6, d = li & 63;
            KT[j * TS + d] = g_kv[(bh * Mm + j0 + j) * Dd + d];  // [j][d] = k-major
        }
        for (int idx = tid; idx < 4096; idx += 256) {
            int jj = idx >> 6, ii = idx & 63;
            float e = dots[ii * 513 + j0 + jj];
            float e2 = e * e, e4 = e2 * e2, e8 = e4 * e4, e16 = e8 * e8;
            int gi = (bh * Mm + j0 + jj) * Nn + i0 + ii;
            float kr = krd[gi];
            o4[gi] = (e16 * e8) * rs2[ii] * kr;
            Ps[jj * TS + ii] = e * rs1[ii] * kr;
        }
        __syncthreads();
#pragma unroll 16
        for (int k = 0; k < 64; k++) {
            ull b0 = *(const ull*)(KT + k * TS + tx * 4);
            ull b1 = *(const ull*)(KT + k * TS + tx * 4 + 2);
#pragma unroll
            for (int r = 0; r < 4; r++) {
                ull ap = pack2s(Ps[k * TS + ty * 4 + r]);
                FMA2(acc2[r][0], ap, b0);
                FMA2(acc2[r][1], ap, b1);
            }
        }
    }
#pragma unroll
    for (int r = 0; r < 4; r++) {
        float v0, v1, v2, v3;
        unpack2(acc2[r][0], v0, v1);
        unpack2(acc2[r][1], v2, v3);
        float* op = g_att + (bh * Nn + i0 + ty * 4 + r) * Dd + tx * 4;
        op[0] = v0; op[1] = v1; op[2] = v2; op[3] = v3;
    }
}

// ---------------- branch 2: k_q vs t_k, flash-style online softmax ----------
__global__ __launch_bounds__(256) void branch2_kernel(const float* __restrict__ krd)
{
    extern __shared__ float sm[];
    float* Qs  = sm;               // [i][d]
    float* KsT = Qs + 64 * TS;     // [d][j]
    float* Vs  = KsT + 64 * TS;    // [j][d] (k-major for PV)
    float* Ss  = Vs + 64 * TS;     // [i][j] logits -> exp
    float* Ps  = Ss + 64 * TS;     // [j][i]
    float* mxA = Ps + 64 * TS;     // 64
    float* dnA = mxA + 64;         // 64
    float* fsc = dnA + 64;         // 64

    int bh = blockIdx.y;
    int i0 = blockIdx.x * 64;
    int tid = threadIdx.x, tx = tid & 15, ty = tid >> 4;
    int w = tid >> 5, lane = tid & 31;

    for (int li = tid; li < 4096; li += 256) {
        int i = li >> 6, d = li & 63;
        Qs[i * TS + d] = g_kq[(bh * Mm + i0 + i) * Dd + d];
    }
    if (tid < 64) { mxA[tid] = -INFINITY; dnA[tid] = 0.f; }

    ull acc[4][2];
#pragma unroll
    for (int r = 0; r < 4; r++) { acc[r][0] = 0ull; acc[r][1] = 0ull; }

    for (int nt = 0; nt < 32; nt++) {
        int n0 = nt * 64;
        __syncthreads();
        for (int li = tid; li < 4096; li += 256) {
            int j = li >> 6, d = li & 63;
            KsT[d * TS + j] = g_tk[(bh * Nn + n0 + j) * Dd + d];
            Vs[j * TS + d]  = g_tv[(bh * Nn + n0 + j) * Dd + d];
        }
        __syncthreads();
        // S = Q @ K^T * scale
        {
            ull sac[4][2];
#pragma unroll
            for (int r = 0; r < 4; r++) { sac[r][0] = 0ull; sac[r][1] = 0ull; }
#pragma unroll 16
            for (int k = 0; k < 64; k++) {
                ull b0 = *(const ull*)(KsT + k * TS + tx * 4);
                ull b1 = *(const ull*)(KsT + k * TS + tx * 4 + 2);
#pragma unroll
                for (int r = 0; r < 4; r++) {
                    ull ap = pack2s(Qs[(ty * 4 + r) * TS + k]);
                    FMA2(sac[r][0], ap, b0);
                    FMA2(sac[r][1], ap, b1);
                }
            }
#pragma unroll
            for (int r = 0; r < 4; r++) {
                float v0, v1, v2, v3;
                unpack2(sac[r][0], v0, v1);
                unpack2(sac[r][1], v2, v3);
                float* sp = Ss + (ty * 4 + r) * TS + tx * 4;
                sp[0] = v0 * SCALEc; sp[1] = v1 * SCALEc;
                sp[2] = v2 * SCALEc; sp[3] = v3 * SCALEc;
            }
        }
        __syncthreads();
        // mask (transposed att_mask; coalesced over ii)
        for (int idx = tid; idx < 4096; idx += 256) {
            int jj = idx >> 6, ii = idx & 63;
            if (g_mask[(bh * Nn + n0 + jj) * Mm + i0 + ii]) Ss[ii * TS + jj] = NEGc;
        }
        __syncthreads();
        // online softmax stats; store e in Ss
        for (int r = 0; r < 8; r++) {
            int i = w * 8 + r;
            float tmx = -INFINITY;
            for (int j = lane; j < 64; j += 32) tmx = fmaxf(tmx, Ss[i * TS + j]);
#pragma unroll
            for (int o = 16; o; o >>= 1) tmx = fmaxf(tmx, __shfl_xor_sync(0xffffffffu, tmx, o));
            float om = mxA[i];
            float nm = fmaxf(om, tmx);
            float s = 0.f;
            for (int j = lane; j < 64; j += 32) {
                float e = __expf(Ss[i * TS + j] - nm);
                Ss[i * TS + j] = e;
                s += e;
            }
#pragma unroll
            for (int o = 16; o; o >>= 1) s += __shfl_xor_sync(0xffffffffu, s, o);
            if (lane == 0) {
                float f = __expf(om - nm);
                dnA[i] = dnA[i] * f + s;
                mxA[i] = nm;
                fsc[i] = f;
            }
        }
        __syncthreads();
        // P = e * krd
        for (int idx = tid; idx < 4096; idx += 256) {
            int ii = idx >> 6, jj = idx & 63;
            float kr = krd[(bh * Mm + i0 + ii) * Nn + n0 + jj];
            Ps[jj * TS + ii] = Ss[ii * TS + jj] * kr;
        }
        __syncthreads();
        // rescale + accumulate P @ V
#pragma unroll
        for (int r = 0; r < 4; r++) {
            ull fp = pack2s(fsc[ty * 4 + r]);
            MUL2(acc[r][0], fp);
            MUL2(acc[r][1], fp);
        }
#pragma unroll 16
        for (int k = 0; k < 64; k++) {
            ull b0 = *(const ull*)(Vs + k * TS + tx * 4);
            ull b1 = *(const ull*)(Vs + k * TS + tx * 4 + 2);
#pragma unroll
            for (int r = 0; r < 4; r++) {
                ull ap = pack2s(Ps[k * TS + ty * 4 + r]);
                FMA2(acc[r][0], ap, b0);
                FMA2(acc[r][1], ap, b1);
            }
        }
    }
    __syncthreads();
#pragma unroll
    for (int r = 0; r < 4; r++) {
        float inv = 1.f / dnA[ty * 4 + r];
        float v0, v1, v2, v3;
        unpack2(acc[r][0], v0, v1);
        unpack2(acc[r][1], v2, v3);
        float* op = g_kout + (bh * Mm + i0 + ty * 4 + r) * Dd + tx * 4;
        op[0] = v0 * inv; op[1] = v1 * inv; op[2] = v2 * inv; op[3] = v3 * inv;
    }
}

// ---------------- branch 3: cluster query (1 per b,h) -----------------------
__global__ __launch_bounds__(256) void branch3_kernel()
{
    __shared__ float cq[64];
    __shared__ float pb[512];
    __shared__ float red[8];
    __shared__ float outp[256];
    __shared__ float smax, ssum;
    int bh = blockIdx.x;
    int b = bh / Hh, h = bh % Hh;
    int tid = threadIdx.x, w = tid >> 5, lane = tid & 31;

    if (tid < 64) cq[tid] = g_cq[bh * Dd + tid];
    __syncthreads();

    for (int j = tid; j < 512; j += 256) {
        float s = 0.f;
#pragma unroll 16
        for (int d = 0; d < 64; d++) s = fmaf(cq[d], g_kk[(bh * Mm + j) * Dd + d], s);
        s *= SCALEc;
        if (g_mask[(size_t)(bh * Nn) * Mm + j]) s = NEGc;
        pb[j] = s;
    }
    __syncthreads();
    float m = -INFINITY;
    for (int j = tid; j < 512; j += 256) m = fmaxf(m, pb[j]);
#pragma unroll
    for (int o = 16; o; o >>= 1) m = fmaxf(m, __shfl_xor_sync(0xffffffffu, m, o));
    if (lane == 0) red[w] = m;
    __syncthreads();
    if (tid == 0) {
        float mm = red[0];
        for (int i = 1; i < 8; i++) mm = fmaxf(mm, red[i]);
        smax = mm;
    }
    __syncthreads();
    float sum = 0.f;
    for (int j = tid; j < 512; j += 256) {
        float e = __expf(pb[j] - smax);
        pb[j] = e;
        sum += e;
    }
#pragma unroll
    for (int o = 16; o; o >>= 1) sum += __shfl_xor_sync(0xffffffffu, sum, o);
    if (lane == 0) red[w] = sum;
    __syncthreads();
    if (tid == 0) {
        float s = 0.f;
        for (int i = 0; i < 8; i++) s += red[i];
        ssum = s;
    }
    __syncthreads();
    int d = tid & 63, q = tid >> 6;
    float a = 0.f;
    for (int j = q * 128; j < (q + 1) * 128; j++)
        a = fmaf(pb[j], g_kv[(bh * Mm + j) * Dd + d], a);
    outp[q * 64 + d] = a;
    __syncthreads();
    if (tid < 64) {
        float tot = outp[tid] + outp[64 + tid] + outp[128 + tid] + outp[192 + tid];
        g_cout[b * DIMc + h * Dd + tid] = tot / ssum;
    }
}

// ---------------- cluster projection ----------------------------------------
__global__ __launch_bounds__(256) void cproj_kernel(
    const float* __restrict__ W, const float* __restrict__ bias,
    float* __restrict__ o3)
{
    int gid = blockIdx.x * 256 + threadIdx.x;  // 3072 total
    int b = gid / 768, c = gid % 768;
    float a = bias[c];
    for (int k = 0; k < 768; k++) a = fmaf(g_cout[b * 768 + k], W[k * 768 + c], a);
    o3[gid] = a;
}

// ---------------- launch ----------------------------------------------------
extern "C" void kernel_launch(void* const* d_in, const int* in_sizes, int n_in,
                              void* d_out, int out_size) {
    const float* x    = (const float*)d_in[0];
    const float* kx   = (const float*)d_in[1];
    const float* krd  = (const float*)d_in[2];
    const float* clst = (const float*)d_in[3];
    const void*  amsk = d_in[4];
    const float* Wqkv = (const float*)d_in[5];
    const float* Wout = (const float*)d_in[6];
    const float* bout = (const float*)d_in[7];
    float* out = (float*)d_out;

    float* o1 = out + O1_OFF;
    float* o2 = out + O2_OFF;
    float* o3 = out + O3_OFF;
    float* o4 = out + O4_OFF;

    size_t sm1 = (size_t)(64 * TS * 3 + 64 * 513 + 128) * 4;
    size_t sm2 = (size_t)(64 * TS * 5 + 192) * 4;
    cudaFuncSetAttribute(branch1_kernel, cudaFuncAttributeMaxDynamicSharedMemorySize, (int)sm1);
    cudaFuncSetAttribute(branch2_kernel, cudaFuncAttributeMaxDynamicSharedMemorySize, (int)sm2);

    detect_mask_kernel<<<1, 256>>>(amsk);
    norm_mask_kernel<<<MASK_ELEMS / 4 / 256, 256>>>(amsk);

    // QKV projections
    gemm_qkv_kernel<<<dim3(18, 64), 256>>>(x,    Wqkv, 8192, 2048, 0);
    gemm_qkv_kernel<<<dim3(18, 16), 256>>>(kx,   Wqkv, 2048,  512, 1);
    gemm_qkv_kernel<<<dim3(18,  1), 256>>>(clst, Wqkv,    4,    1, 2);

    // attention branches
    branch1_kernel<<<dim3(32, 48), 256, sm1>>>(krd, o4);
    branch2_kernel<<<dim3(8,  48), 256, sm2>>>(krd);
    branch3_kernel<<<48, 256>>>();

    // output projections
    gemm_proj_kernel<<<dim3(6, 64), 256>>>(Wout, bout, o1, 8192, 2048, 0);
    gemm_proj_kernel<<<dim3(6, 16), 256>>>(Wout, bout, o2, 2048,  512, 1);
    cproj_kernel<<<12, 256>>>(Wout, bout, o3);
}